// round 14
// baseline (speedup 1.0000x reference)
#include <cuda_runtime.h>
#include <cuda_fp16.h>
#include <cstdint>

// Problem constants
#define NB    8
#define ND    256
#define NTHW  16384
#define NTOK  131072
#define NK    1024
#define NTOT  (NTOK * ND)
#define CMAX  32

// Fused kernel tiling: 64 tokens/block, 16 tiles of 64 codes, 2 blocks/SM
#define MT    64
#define PADH  264    // fp16 row stride (elements) -> 528B rows, 16B aligned
#define QST   260    // qs row stride (floats)

// smem offsets (bytes)
#define OFF_XH    0                        // [64][264] fp16        33792
#define OFF_E0    33792                    // [64][264] fp16        33792 (later: qs)
#define OFF_E1    67584                    // [64][264] fp16 (A/S scratch pre-loop; later qs)
#define OFF_SB    101376                   // [1024] f32            4096
#define OFF_CNT   105472                   // [64] int              256
#define OFF_WMIN  105728                   // [64][2] f32           512
#define OFF_ATOK  106240                   // [64] f32              256
#define OFF_MARG  106496                   // [64] f32 (later thrF) 256
#define OFF_SBI   106752                   // [64] int              256
#define OFF_RED   107008                   // [8] double            64
#define SMEM_FUSED 107072

__device__ int2   g_cand[(size_t)NTOK * CMAX];
__device__ float  g_B[NK];
__device__ __align__(16) __half g_embh[(size_t)NK * ND];
__device__ double g_loss;

__device__ __forceinline__ uint32_t s2u(const void* p) {
    return (uint32_t)__cvta_generic_to_shared(p);
}
__device__ __forceinline__ void ldmA(uint32_t& a0, uint32_t& a1, uint32_t& a2, uint32_t& a3, uint32_t addr) {
    asm volatile("ldmatrix.sync.aligned.m8n8.x4.shared.b16 {%0,%1,%2,%3}, [%4];"
                 : "=r"(a0), "=r"(a1), "=r"(a2), "=r"(a3) : "r"(addr));
}
__device__ __forceinline__ void ldmB4(uint32_t& b0, uint32_t& b1, uint32_t& b2, uint32_t& b3, uint32_t addr) {
    asm volatile("ldmatrix.sync.aligned.m8n8.x4.shared.b16 {%0,%1,%2,%3}, [%4];"
                 : "=r"(b0), "=r"(b1), "=r"(b2), "=r"(b3) : "r"(addr));
}
__device__ __forceinline__ void mma16816(float* c, uint32_t a0, uint32_t a1, uint32_t a2, uint32_t a3,
                                         uint32_t b0, uint32_t b1) {
    asm volatile("mma.sync.aligned.m16n8k16.row.col.f32.f16.f16.f32 "
                 "{%0,%1,%2,%3}, {%4,%5,%6,%7}, {%8,%9}, {%0,%1,%2,%3};"
                 : "+f"(c[0]), "+f"(c[1]), "+f"(c[2]), "+f"(c[3])
                 : "r"(a0), "r"(a1), "r"(a2), "r"(a3), "r"(b0), "r"(b1));
}

// Async-stage one 64-code x 256-ch fp16 emb tile (32KB) into smem buffer.
__device__ __forceinline__ void stage_e_async(uint32_t dstb, const __half* __restrict__ embh,
                                              int ks, int tid) {
    const char* src = (const char*)(embh + (size_t)ks * 64 * ND);
    #pragma unroll
    for (int j = 0; j < 8; j++) {
        int l = tid + j * 256;                 // 0..2047 chunks of 16B
        int r = l >> 5, g = l & 31;
        uint32_t dst = dstb + (uint32_t)(r * (PADH * 2) + g * 16);
        const char* s = src + r * 512 + g * 16;
        asm volatile("cp.async.cg.shared.global [%0], [%1], 16;" :: "r"(dst), "l"(s) : "memory");
    }
}

// Exact distance, bit-identical R1 arithmetic: ascending-c fmaf chain on
// fp32 x (gmem scalars) and fp32 emb, then fl(fl(A+B) - 2M).
__device__ __forceinline__ float exact_d(const float* __restrict__ xb,
                                         const float* __restrict__ emb,
                                         int t, int k, float A, float Bk) {
    const float4* er4 = reinterpret_cast<const float4*>(emb + (size_t)k * ND);
    float av = 0.f;
    #pragma unroll 8
    for (int c4 = 0; c4 < 64; c4++) {
        float4 e = er4[c4];
        av = fmaf(__ldg(xb + (size_t)(4 * c4 + 0) * NTHW + t), e.x, av);
        av = fmaf(__ldg(xb + (size_t)(4 * c4 + 1) * NTHW + t), e.y, av);
        av = fmaf(__ldg(xb + (size_t)(4 * c4 + 2) * NTHW + t), e.z, av);
        av = fmaf(__ldg(xb + (size_t)(4 * c4 + 3) * NTHW + t), e.w, av);
    }
    float ab = __fadd_rn(A, Bk);
    return __fadd_rn(ab, __fmul_rn(-2.0f, av));
}

// ---------------------------------------------------------------------------
// Kernel 0: zero loss + B_k (sequential rounded chain) + fp16 codebook copy
// ---------------------------------------------------------------------------
__global__ void k_init(const float* __restrict__ emb) {
    int k = blockIdx.x * blockDim.x + threadIdx.x;
    if (k == 0) g_loss = 0.0;
    if (k < NK) {
        const float* r = emb + (size_t)k * ND;
        __half* eh = g_embh + (size_t)k * ND;
        float a = 0.f;
        #pragma unroll 8
        for (int c = 0; c < ND; c++) {
            float v = r[c];
            a = __fadd_rn(a, __fmul_rn(v, v));
            eh[c] = __float2half_rn(v);
        }
        g_B[k] = a;
    }
}

// ---------------------------------------------------------------------------
// Kernel 1: FUSED screen + rescore + gather + output + loss.
// Screen: fp16 MMA (fp32 acc, R4 numerics) with fused A/S/margin, cp.async
// double-buffered e-tiles (identical to the 607us kernel's k_screen).
// Epilogue (in-block, overlaps co-resident block's MMA): count==1 argmin
// shortcut / exact fmaf-chain dots, winner gather into freed E-smem,
// straight-through output + loss.
// ---------------------------------------------------------------------------
__global__ __launch_bounds__(256) void k_fused(const float* __restrict__ x,
                                               const float* __restrict__ emb,
                                               float* __restrict__ out) {
    extern __shared__ char sm[];
    __half* xh    = (__half*)(sm + OFF_XH);     // [64][264]
    float*  scr   = (float*)(sm + OFF_E1);      // A/S scratch (pre-loop only)
    float*  sB    = (float*)(sm + OFF_SB);      // [1024]
    int*    cnt   = (int*)(sm + OFF_CNT);       // [64]
    float*  wmin  = (float*)(sm + OFF_WMIN);    // [64][2]
    float*  aTok  = (float*)(sm + OFF_ATOK);    // [64]
    float*  mTok  = (float*)(sm + OFF_MARG);    // [64] margin -> thrF
    int*    sbi   = (int*)(sm + OFF_SBI);       // [64]
    double* red   = (double*)(sm + OFF_RED);    // [8]

    int tid = threadIdx.x;
    int n0  = blockIdx.x * MT;
    int b   = n0 / NTHW;
    int p0  = n0 % NTHW;
    const float* xb = x + (size_t)b * ND * NTHW + p0;

    stage_e_async(s2u(sm + OFF_E0), g_embh, 0, tid);
    asm volatile("cp.async.commit_group;" ::: "memory");

    // x tile -> fp16 + fused A/S partials
    int t4s = (tid & 15) * 4;
    int cp0 = tid >> 4;
    float pA[4] = {0.f, 0.f, 0.f, 0.f};
    float pS[4] = {0.f, 0.f, 0.f, 0.f};
    #pragma unroll
    for (int i = 0; i < 16; i++) {
        int c = cp0 + 16 * i;
        float4 v = *reinterpret_cast<const float4*>(xb + (size_t)c * NTHW + t4s);
        xh[(t4s + 0) * PADH + c] = __float2half_rn(v.x);
        xh[(t4s + 1) * PADH + c] = __float2half_rn(v.y);
        xh[(t4s + 2) * PADH + c] = __float2half_rn(v.z);
        xh[(t4s + 3) * PADH + c] = __float2half_rn(v.w);
        pA[0] = __fadd_rn(pA[0], __fmul_rn(v.x, v.x));  pS[0] += fabsf(v.x);
        pA[1] = __fadd_rn(pA[1], __fmul_rn(v.y, v.y));  pS[1] += fabsf(v.y);
        pA[2] = __fadd_rn(pA[2], __fmul_rn(v.z, v.z));  pS[2] += fabsf(v.z);
        pA[3] = __fadd_rn(pA[3], __fmul_rn(v.w, v.w));  pS[3] += fabsf(v.w);
    }
    #pragma unroll
    for (int j = 0; j < 4; j++) {
        scr[(t4s + j) * 32 + cp0]      = pA[j];
        scr[(t4s + j) * 32 + 16 + cp0] = pS[j];
    }
    for (int l = tid; l < NK; l += 256) sB[l] = g_B[l];
    if (tid < MT) cnt[tid] = 0;
    __syncthreads();

    if (tid < MT) {
        float A = 0.f, S = 0.f;
        #pragma unroll
        for (int p = 0; p < 16; p++) {
            A = __fadd_rn(A, scr[tid * 32 + p]);
            S += scr[tid * 32 + 16 + p];
        }
        aTok[tid] = A;
        mTok[tid] = S * 1e-6f + 1.5e-4f;
    }
    __syncthreads();   // scratch (E1) free after this point

    int w = tid >> 5, lane = tid & 31;
    int wt    = (w & 3) * 16;
    int chalf = w >> 2;
    int gid = lane >> 2, tig = lane & 3;
    int rl = wt + gid, rh = rl + 8;
    float margL = mTok[rl], margH = mTok[rh];
    float minL = __int_as_float(0x7f800000), minH = minL;

    int am = lane >> 3, arr = lane & 7;
    uint32_t aBase = s2u(xh) + (uint32_t)(((wt + ((am & 1) << 3) + arr) * PADH + ((am >> 1) << 3)) * 2);
    int brr = lane & 7, bm = (lane >> 3) & 1, bgrp = lane >> 4;
    uint32_t bFrag = (uint32_t)(((chalf * 32 + bgrp * 8 + brr) * PADH + bm * 8) * 2);

    for (int i = 0; i < 16; i++) {
        asm volatile("cp.async.wait_group 0;" ::: "memory");
        __syncthreads();
        if (i < 15) {
            stage_e_async(s2u(sm + (((i + 1) & 1) ? OFF_E1 : OFF_E0)), g_embh, i + 1, tid);
            asm volatile("cp.async.commit_group;" ::: "memory");
        }
        uint32_t bBase = s2u(sm + ((i & 1) ? OFF_E1 : OFF_E0)) + bFrag;

        float acc[4][4];
        #pragma unroll
        for (int nt = 0; nt < 4; nt++)
            #pragma unroll
            for (int c = 0; c < 4; c++) acc[nt][c] = 0.f;

        #pragma unroll 4
        for (int kc = 0; kc < 16; kc++) {
            uint32_t a0, a1, a2, a3;
            ldmA(a0, a1, a2, a3, aBase + kc * 32);
            #pragma unroll
            for (int nt = 0; nt < 4; nt += 2) {
                uint32_t b0, b1, b2, b3;
                ldmB4(b0, b1, b2, b3, bBase + (uint32_t)(nt * 8 * PADH * 2) + kc * 32);
                mma16816(acc[nt],     a0, a1, a2, a3, b0, b1);
                mma16816(acc[nt + 1], a0, a1, a2, a3, b2, b3);
            }
        }

        int nbase = i * 64 + chalf * 32;
        float tminL = minL, tminH = minH;
        #pragma unroll
        for (int nt = 0; nt < 4; nt++) {
            #pragma unroll
            for (int c = 0; c < 4; c++) {
                int n = nbase + nt * 8 + 2 * tig + (c & 1);
                float h = fmaf(-2.f, acc[nt][c], sB[n]);
                acc[nt][c] = h;
                if (c < 2) tminL = fminf(tminL, h); else tminH = fminf(tminH, h);
            }
        }
        minL = tminL; minH = tminH;
        float qL = minL, qH = minH;
        qL = fminf(qL, __shfl_xor_sync(0xffffffffu, qL, 1));
        qL = fminf(qL, __shfl_xor_sync(0xffffffffu, qL, 2));
        qH = fminf(qH, __shfl_xor_sync(0xffffffffu, qH, 1));
        qH = fminf(qH, __shfl_xor_sync(0xffffffffu, qH, 2));
        float thrL = qL + margL, thrH = qH + margH;

        #pragma unroll
        for (int nt = 0; nt < 4; nt++) {
            #pragma unroll
            for (int c = 0; c < 4; c++) {
                float h   = acc[nt][c];
                float thr = (c < 2) ? thrL : thrH;
                if (h <= thr) {
                    int row = (c < 2) ? rl : rh;
                    int n   = nbase + nt * 8 + 2 * tig + (c & 1);
                    int p = atomicAdd(&cnt[row], 1);
                    if (p < CMAX)
                        g_cand[(size_t)(n0 + row) * CMAX + p] = make_int2(n, __float_as_int(h));
                }
            }
        }
    }

    if (tig == 0) {
        wmin[rl * 2 + chalf] = minL;
        wmin[rh * 2 + chalf] = minH;
    }
    __syncthreads();
    if (tid < MT)
        mTok[tid] = fminf(wmin[tid * 2], wmin[tid * 2 + 1]) + mTok[tid];   // thrF
    __syncthreads();

    // ---------------- rescore: 4 threads per token ----------------
    {
        int t   = tid >> 2;
        int j0v = tid & 3;
        unsigned gmask = 0xFu << (lane & 28);
        int gn = n0 + t;
        int cN = cnt[t];
        float thrF = mTok[t];
        float A    = aTok[t];

        if (cN <= CMAX) {
            int sk[2];
            int nLoc = 0;
            for (int j = j0v; j < cN; j += 4) {
                int2 ce = g_cand[(size_t)gn * CMAX + j];
                if (__int_as_float(ce.y) <= thrF) {
                    if (nLoc < 2) sk[nLoc] = ce.x;
                    nLoc++;
                }
            }
            int total = nLoc;
            int mink  = nLoc ? sk[0] : 0x7fffffff;
            #pragma unroll
            for (int off = 1; off < 4; off <<= 1) {
                total += __shfl_xor_sync(gmask, total, off);
                mink = min(mink, __shfl_xor_sync(gmask, mink, off));
            }
            if (total == 1) {
                if (j0v == 0) sbi[t] = mink;   // sole survivor = exact argmin
            } else {
                float bd = __int_as_float(0x7f800000);
                int   bi = 0x7fffffff;
                for (int s = 0; s < nLoc && s < 2; s++) {
                    int k = sk[s];
                    float d = exact_d(xb, emb, t, k, A, sB[k]);
                    if (d < bd || (d == bd && k < bi)) { bd = d; bi = k; }
                }
                if (nLoc > 2) {
                    int seen = 0;
                    for (int j = j0v; j < cN; j += 4) {
                        int2 ce = g_cand[(size_t)gn * CMAX + j];
                        if (__int_as_float(ce.y) > thrF) continue;
                        if (++seen <= 2) continue;
                        int k = ce.x;
                        float d = exact_d(xb, emb, t, k, A, sB[k]);
                        if (d < bd || (d == bd && k < bi)) { bd = d; bi = k; }
                    }
                }
                #pragma unroll
                for (int off = 1; off < 4; off <<= 1) {
                    float od = __shfl_xor_sync(gmask, bd, off);
                    int   oi = __shfl_xor_sync(gmask, bi, off);
                    if (od < bd || (od == bd && oi < bi)) { bd = od; bi = oi; }
                }
                if (j0v == 0) sbi[t] = bi;
            }
        } else {
            // overflow fallback: exact scan of all codes (P ~ 0)
            float bd = __int_as_float(0x7f800000);
            int   bi = 0x7fffffff;
            for (int k = j0v; k < NK; k += 4) {
                float d = exact_d(xb, emb, t, k, A, sB[k]);
                if (d < bd || (d == bd && k < bi)) { bd = d; bi = k; }
            }
            #pragma unroll
            for (int off = 1; off < 4; off <<= 1) {
                float od = __shfl_xor_sync(gmask, bd, off);
                int   oi = __shfl_xor_sync(gmask, bi, off);
                if (od < bd || (od == bd && oi < bi)) { bd = od; bi = oi; }
            }
            if (j0v == 0) sbi[t] = bi;
        }
    }
    __syncthreads();

    // ---------------- gather winner rows into freed E-smem ----------------
    float* qs = (float*)(sm + OFF_E0);           // [64][260]
    #pragma unroll
    for (int rr = 0; rr < 8; rr++) {
        int r = w * 8 + rr;
        const float4* er = reinterpret_cast<const float4*>(emb + (size_t)sbi[r] * ND);
        #pragma unroll
        for (int u = 0; u < 2; u++)
            *reinterpret_cast<float4*>(qs + r * QST + u * 128 + lane * 4) = er[u * 32 + lane];
    }
    __syncthreads();

    // ---------------- straight-through output + loss ----------------
    float* ob = out + (size_t)b * ND * NTHW + p0;
    double lacc = 0.0;
    #pragma unroll
    for (int i = 0; i < 16; i++) {
        int o  = tid + i * 256;          // [0, 4096)
        int c  = o >> 4, t4 = (o & 15) * 4;
        float4 xv = *reinterpret_cast<const float4*>(xb + (size_t)c * NTHW + t4);
        float d0 = __fsub_rn(qs[(t4 + 0) * QST + c], xv.x);
        float d1 = __fsub_rn(qs[(t4 + 1) * QST + c], xv.y);
        float d2 = __fsub_rn(qs[(t4 + 2) * QST + c], xv.z);
        float d3 = __fsub_rn(qs[(t4 + 3) * QST + c], xv.w);
        float4 ov;
        ov.x = __fadd_rn(xv.x, d0); ov.y = __fadd_rn(xv.y, d1);
        ov.z = __fadd_rn(xv.z, d2); ov.w = __fadd_rn(xv.w, d3);
        *reinterpret_cast<float4*>(ob + (size_t)c * NTHW + t4) = ov;
        lacc += (double)__fmul_rn(d0, d0) + (double)__fmul_rn(d1, d1)
              + (double)__fmul_rn(d2, d2) + (double)__fmul_rn(d3, d3);
    }
    #pragma unroll
    for (int off = 16; off > 0; off >>= 1)
        lacc += __shfl_down_sync(0xffffffffu, lacc, off);
    if (lane == 0) red[w] = lacc;
    __syncthreads();
    if (tid == 0) {
        double s = 0.0;
        #pragma unroll
        for (int i = 0; i < 8; i++) s += red[i];
        atomicAdd(&g_loss, s);
    }
}

// ---------------------------------------------------------------------------
// Kernel 2: finalize loss
// ---------------------------------------------------------------------------
__global__ void k_final(float* __restrict__ out, int out_size) {
    if (out_size > NTOT) {
        float m = (float)(g_loss / (double)NTOT);
        out[NTOT] = __fadd_rn(m, __fmul_rn(0.25f, m));
    }
}

// ---------------------------------------------------------------------------
extern "C" void kernel_launch(void* const* d_in, const int* in_sizes, int n_in,
                              void* d_out, int out_size) {
    const float* x   = (const float*)d_in[0];
    const float* emb = (const float*)d_in[1];
    if (n_in >= 2 && in_sizes[0] == NK * ND && in_sizes[1] == NTOT) {
        x   = (const float*)d_in[1];
        emb = (const float*)d_in[0];
    }
    float* out = (float*)d_out;

    cudaFuncSetAttribute(k_fused, cudaFuncAttributeMaxDynamicSharedMemorySize, SMEM_FUSED);

    k_init <<<(NK + 255) / 256, 256>>>(emb);
    k_fused<<<NTOK / MT, 256, SMEM_FUSED>>>(x, emb, out);
    k_final<<<1, 1>>>(out, out_size);
}

// round 15
// speedup vs baseline: 1.0989x; 1.0989x over previous
#include <cuda_runtime.h>
#include <cuda_fp16.h>
#include <cstdint>

// Problem constants
#define NB    8
#define ND    256
#define NTHW  16384
#define NTOK  131072
#define NK    1024
#define NTOT  (NTOK * ND)
#define CMAX  32

// Screen tiling: 64 tokens/block, 16 tiles of 64 codes, 2 blocks/SM
#define MT    64
#define PADH  264    // fp16 row stride (elements) -> 528B rows, 16B aligned

// Screen smem offsets (bytes)
#define OFF_XH    0                        // [64][264] fp16        33792
#define OFF_E0    33792                    // [64][264] fp16        33792
#define OFF_E1    67584                    // [64][264] fp16 (also A/S scratch pre-loop)
#define OFF_SB    101376                   // [1024] f32            4096
#define OFF_CNT   105472                   // [64] int              256
#define OFF_WMIN  105728                   // [64][2] f32           512
#define OFF_ATOK  106240                   // [64] f32              256
#define OFF_MARG  106496                   // [64] f32              256
#define SMEM_SCREEN 106752

// Rescore+gather (16 tokens/block, 256 threads, 6 blocks/SM)
#define RT   16
#define RST  20
#define QST  260
#define ROFF_QS  (ND * RST * 4)            // 20480
#define ROFF_BI  (ROFF_QS + RT * QST * 4)  // 37120
#define ROFF_RED (ROFF_BI + 64)            // 37184
#define SMEM_RESG (ROFF_RED + 64)          // 37248

__device__ int    g_cnt[NTOK];
__device__ float  g_thr[NTOK];
__device__ int2   g_cand[(size_t)NTOK * CMAX];
__device__ float  g_A[NTOK];
__device__ float  g_B[NK];
__device__ __align__(16) __half g_embh[(size_t)NK * ND];
__device__ double g_loss;

__device__ __forceinline__ uint32_t s2u(const void* p) {
    return (uint32_t)__cvta_generic_to_shared(p);
}
__device__ __forceinline__ void ldmA(uint32_t& a0, uint32_t& a1, uint32_t& a2, uint32_t& a3, uint32_t addr) {
    asm volatile("ldmatrix.sync.aligned.m8n8.x4.shared.b16 {%0,%1,%2,%3}, [%4];"
                 : "=r"(a0), "=r"(a1), "=r"(a2), "=r"(a3) : "r"(addr));
}
__device__ __forceinline__ void ldmB4(uint32_t& b0, uint32_t& b1, uint32_t& b2, uint32_t& b3, uint32_t addr) {
    asm volatile("ldmatrix.sync.aligned.m8n8.x4.shared.b16 {%0,%1,%2,%3}, [%4];"
                 : "=r"(b0), "=r"(b1), "=r"(b2), "=r"(b3) : "r"(addr));
}
__device__ __forceinline__ void mma16816(float* c, uint32_t a0, uint32_t a1, uint32_t a2, uint32_t a3,
                                         uint32_t b0, uint32_t b1) {
    asm volatile("mma.sync.aligned.m16n8k16.row.col.f32.f16.f16.f32 "
                 "{%0,%1,%2,%3}, {%4,%5,%6,%7}, {%8,%9}, {%0,%1,%2,%3};"
                 : "+f"(c[0]), "+f"(c[1]), "+f"(c[2]), "+f"(c[3])
                 : "r"(a0), "r"(a1), "r"(a2), "r"(a3), "r"(b0), "r"(b1));
}

// Async-stage one 64-code x 256-ch fp16 emb tile (32KB) into smem buffer.
__device__ __forceinline__ void stage_e_async(uint32_t dstb, const __half* __restrict__ embh,
                                              int ks, int tid) {
    const char* src = (const char*)(embh + (size_t)ks * 64 * ND);
    #pragma unroll
    for (int j = 0; j < 8; j++) {
        int l = tid + j * 256;                 // 0..2047 chunks of 16B
        int r = l >> 5, g = l & 31;
        uint32_t dst = dstb + (uint32_t)(r * (PADH * 2) + g * 16);
        const char* s = src + r * 512 + g * 16;
        asm volatile("cp.async.cg.shared.global [%0], [%1], 16;" :: "r"(dst), "l"(s) : "memory");
    }
}

// ---------------------------------------------------------------------------
// Kernel 0: zero loss + B_k + fp16 codebook copy — warp per codeword,
// fully coalesced (float4 lanes), shfl-tree reduction.
// ---------------------------------------------------------------------------
__global__ __launch_bounds__(256) void k_init(const float* __restrict__ emb) {
    int tid  = threadIdx.x;
    int w    = tid >> 5, lane = tid & 31;
    int k    = blockIdx.x * 8 + w;
    if (blockIdx.x == 0 && tid == 0) g_loss = 0.0;

    const float4* er = reinterpret_cast<const float4*>(emb + (size_t)k * ND);
    __half2* eh = reinterpret_cast<__half2*>(g_embh + (size_t)k * ND);
    float a = 0.f;
    #pragma unroll
    for (int u = 0; u < 2; u++) {
        float4 v = er[u * 32 + lane];
        eh[(u * 32 + lane) * 2 + 0] = __floats2half2_rn(v.x, v.y);
        eh[(u * 32 + lane) * 2 + 1] = __floats2half2_rn(v.z, v.w);
        a = __fadd_rn(a, __fmul_rn(v.x, v.x));
        a = __fadd_rn(a, __fmul_rn(v.y, v.y));
        a = __fadd_rn(a, __fmul_rn(v.z, v.z));
        a = __fadd_rn(a, __fmul_rn(v.w, v.w));
    }
    #pragma unroll
    for (int off = 16; off > 0; off >>= 1)
        a = __fadd_rn(a, __shfl_down_sync(0xffffffffu, a, off));
    if (lane == 0) g_B[k] = a;
}

// ---------------------------------------------------------------------------
// Kernel 1: fp16 MMA screen (fp32 accumulate) with fused A/S/margin compute.
// Identical to the 607us kernel.
// ---------------------------------------------------------------------------
__global__ __launch_bounds__(256) void k_screen(const float* __restrict__ x) {
    extern __shared__ char sm[];
    __half* xh    = (__half*)(sm + OFF_XH);     // [64][264]
    float*  scr   = (float*)(sm + OFF_E1);      // A/S scratch [64][32] (pre-loop only)
    float*  sB    = (float*)(sm + OFF_SB);      // [1024]
    int*    cnt   = (int*)(sm + OFF_CNT);       // [64]
    float*  wmin  = (float*)(sm + OFF_WMIN);    // [64][2]
    float*  aTok  = (float*)(sm + OFF_ATOK);    // [64]
    float*  mTok  = (float*)(sm + OFF_MARG);    // [64]

    int tid = threadIdx.x;
    int n0  = blockIdx.x * MT;
    int b   = n0 / NTHW;
    int p0  = n0 % NTHW;
    const float* xb = x + (size_t)b * ND * NTHW + p0;

    stage_e_async(s2u(sm + OFF_E0), g_embh, 0, tid);
    asm volatile("cp.async.commit_group;" ::: "memory");

    int t4  = (tid & 15) * 4;
    int cp0 = tid >> 4;
    float pA[4] = {0.f, 0.f, 0.f, 0.f};
    float pS[4] = {0.f, 0.f, 0.f, 0.f};
    #pragma unroll
    for (int i = 0; i < 16; i++) {
        int c = cp0 + 16 * i;
        float4 v = *reinterpret_cast<const float4*>(xb + (size_t)c * NTHW + t4);
        xh[(t4 + 0) * PADH + c] = __float2half_rn(v.x);
        xh[(t4 + 1) * PADH + c] = __float2half_rn(v.y);
        xh[(t4 + 2) * PADH + c] = __float2half_rn(v.z);
        xh[(t4 + 3) * PADH + c] = __float2half_rn(v.w);
        pA[0] = __fadd_rn(pA[0], __fmul_rn(v.x, v.x));  pS[0] += fabsf(v.x);
        pA[1] = __fadd_rn(pA[1], __fmul_rn(v.y, v.y));  pS[1] += fabsf(v.y);
        pA[2] = __fadd_rn(pA[2], __fmul_rn(v.z, v.z));  pS[2] += fabsf(v.z);
        pA[3] = __fadd_rn(pA[3], __fmul_rn(v.w, v.w));  pS[3] += fabsf(v.w);
    }
    #pragma unroll
    for (int j = 0; j < 4; j++) {
        scr[(t4 + j) * 32 + cp0]      = pA[j];
        scr[(t4 + j) * 32 + 16 + cp0] = pS[j];
    }
    for (int l = tid; l < NK; l += 256) sB[l] = g_B[l];
    if (tid < MT) cnt[tid] = 0;
    __syncthreads();

    if (tid < MT) {
        float A = 0.f, S = 0.f;
        #pragma unroll
        for (int p = 0; p < 16; p++) {
            A = __fadd_rn(A, scr[tid * 32 + p]);
            S += scr[tid * 32 + 16 + p];
        }
        aTok[tid] = A;
        mTok[tid] = S * 1e-6f + 1.5e-4f;
        g_A[n0 + tid] = A;
    }
    __syncthreads();   // scratch (E1) free after this point

    int w = tid >> 5, lane = tid & 31;
    int wt    = (w & 3) * 16;
    int chalf = w >> 2;
    int gid = lane >> 2, tig = lane & 3;
    int rl = wt + gid, rh = rl + 8;
    float margL = mTok[rl], margH = mTok[rh];
    float minL = __int_as_float(0x7f800000), minH = minL;

    int am = lane >> 3, arr = lane & 7;
    uint32_t aBase = s2u(xh) + (uint32_t)(((wt + ((am & 1) << 3) + arr) * PADH + ((am >> 1) << 3)) * 2);
    int brr = lane & 7, bm = (lane >> 3) & 1, bgrp = lane >> 4;
    uint32_t bFrag = (uint32_t)(((chalf * 32 + bgrp * 8 + brr) * PADH + bm * 8) * 2);

    for (int i = 0; i < 16; i++) {
        asm volatile("cp.async.wait_group 0;" ::: "memory");
        __syncthreads();
        if (i < 15) {
            stage_e_async(s2u(sm + (((i + 1) & 1) ? OFF_E1 : OFF_E0)), g_embh, i + 1, tid);
            asm volatile("cp.async.commit_group;" ::: "memory");
        }
        uint32_t bBase = s2u(sm + ((i & 1) ? OFF_E1 : OFF_E0)) + bFrag;

        float acc[4][4];
        #pragma unroll
        for (int nt = 0; nt < 4; nt++)
            #pragma unroll
            for (int c = 0; c < 4; c++) acc[nt][c] = 0.f;

        #pragma unroll 4
        for (int kc = 0; kc < 16; kc++) {
            uint32_t a0, a1, a2, a3;
            ldmA(a0, a1, a2, a3, aBase + kc * 32);
            #pragma unroll
            for (int nt = 0; nt < 4; nt += 2) {
                uint32_t b0, b1, b2, b3;
                ldmB4(b0, b1, b2, b3, bBase + (uint32_t)(nt * 8 * PADH * 2) + kc * 32);
                mma16816(acc[nt],     a0, a1, a2, a3, b0, b1);
                mma16816(acc[nt + 1], a0, a1, a2, a3, b2, b3);
            }
        }

        int nbase = i * 64 + chalf * 32;
        float tminL = minL, tminH = minH;
        #pragma unroll
        for (int nt = 0; nt < 4; nt++) {
            #pragma unroll
            for (int c = 0; c < 4; c++) {
                int n = nbase + nt * 8 + 2 * tig + (c & 1);
                float h = fmaf(-2.f, acc[nt][c], sB[n]);
                acc[nt][c] = h;
                if (c < 2) tminL = fminf(tminL, h); else tminH = fminf(tminH, h);
            }
        }
        minL = tminL; minH = tminH;
        float qL = minL, qH = minH;
        qL = fminf(qL, __shfl_xor_sync(0xffffffffu, qL, 1));
        qL = fminf(qL, __shfl_xor_sync(0xffffffffu, qL, 2));
        qH = fminf(qH, __shfl_xor_sync(0xffffffffu, qH, 1));
        qH = fminf(qH, __shfl_xor_sync(0xffffffffu, qH, 2));
        float thrL = qL + margL, thrH = qH + margH;

        #pragma unroll
        for (int nt = 0; nt < 4; nt++) {
            #pragma unroll
            for (int c = 0; c < 4; c++) {
                float h   = acc[nt][c];
                float thr = (c < 2) ? thrL : thrH;
                if (h <= thr) {
                    int row = (c < 2) ? rl : rh;
                    int n   = nbase + nt * 8 + 2 * tig + (c & 1);
                    int p = atomicAdd(&cnt[row], 1);
                    if (p < CMAX)
                        g_cand[(size_t)(n0 + row) * CMAX + p] = make_int2(n, __float_as_int(h));
                }
            }
        }
    }

    if (tig == 0) {
        wmin[rl * 2 + chalf] = minL;
        wmin[rh * 2 + chalf] = minH;
    }
    __syncthreads();
    if (tid < MT) {
        g_thr[n0 + tid] = fminf(wmin[tid * 2], wmin[tid * 2 + 1]) + mTok[tid];
        g_cnt[n0 + tid] = cnt[tid];
    }
}

// ---------------------------------------------------------------------------
// Kernel 2: fused exact rescore + gather + straight-through out + loss.
// 16 tokens/block (R12 structure). Bit-identical R1 rescore arithmetic.
// ---------------------------------------------------------------------------
__global__ __launch_bounds__(256) void k_resg(const float* __restrict__ x,
                                              const float* __restrict__ emb,
                                              float* __restrict__ out) {
    extern __shared__ char sm[];
    float*  xs  = (float*)sm;                    // [256][20] x, [c][t]
    float*  qs  = (float*)(sm + ROFF_QS);        // [16][260] winner codewords
    int*    sbi = (int*)(sm + ROFF_BI);          // [16]
    double* red = (double*)(sm + ROFF_RED);      // [8]

    int tid = threadIdx.x;
    int n0  = blockIdx.x * RT;
    int b   = n0 / NTHW;
    int p0  = n0 % NTHW;
    const float* xb = x + (size_t)b * ND * NTHW + p0;

    #pragma unroll
    for (int i = 0; i < 4; i++) {
        int l  = tid + i * 256;          // [0, 1024)
        int c  = l >> 2, t4 = (l & 3) * 4;
        float4 v = *reinterpret_cast<const float4*>(xb + (size_t)c * NTHW + t4);
        *reinterpret_cast<float4*>(xs + c * RST + t4) = v;
    }
    __syncthreads();

    int t  = tid >> 4;
    int j0 = tid & 15;
    int gn = n0 + t;
    int cN = g_cnt[gn];
    float thrF = g_thr[gn];
    float A    = g_A[gn];
    float bd = __int_as_float(0x7f800000);
    int   bi = 0x7fffffff;

    if (cN <= CMAX) {
        for (int j = j0; j < cN; j += 16) {
            int2 ce = g_cand[(size_t)gn * CMAX + j];
            if (__int_as_float(ce.y) > thrF) continue;
            int k = ce.x;
            const float4* er4 = reinterpret_cast<const float4*>(emb + (size_t)k * ND);
            float av = 0.f;
            #pragma unroll 16
            for (int c4 = 0; c4 < 64; c4++) {
                float4 e = er4[c4];
                av = fmaf(xs[(4 * c4 + 0) * RST + t], e.x, av);
                av = fmaf(xs[(4 * c4 + 1) * RST + t], e.y, av);
                av = fmaf(xs[(4 * c4 + 2) * RST + t], e.z, av);
                av = fmaf(xs[(4 * c4 + 3) * RST + t], e.w, av);
            }
            float ab = __fadd_rn(A, g_B[k]);
            float d  = __fadd_rn(ab, __fmul_rn(-2.0f, av));
            if (d < bd || (d == bd && k < bi)) { bd = d; bi = k; }
        }
    } else {
        for (int k = j0; k < NK; k += 16) {
            const float4* er4 = reinterpret_cast<const float4*>(emb + (size_t)k * ND);
            float av = 0.f;
            #pragma unroll 16
            for (int c4 = 0; c4 < 64; c4++) {
                float4 e = er4[c4];
                av = fmaf(xs[(4 * c4 + 0) * RST + t], e.x, av);
                av = fmaf(xs[(4 * c4 + 1) * RST + t], e.y, av);
                av = fmaf(xs[(4 * c4 + 2) * RST + t], e.z, av);
                av = fmaf(xs[(4 * c4 + 3) * RST + t], e.w, av);
            }
            float ab = __fadd_rn(A, g_B[k]);
            float d  = __fadd_rn(ab, __fmul_rn(-2.0f, av));
            if (d < bd || (d == bd && k < bi)) { bd = d; bi = k; }
        }
    }
    #pragma unroll
    for (int off = 1; off < 16; off <<= 1) {
        float od = __shfl_xor_sync(0xffffffffu, bd, off);
        int   oi = __shfl_xor_sync(0xffffffffu, bi, off);
        if (od < bd || (od == bd && oi < bi)) { bd = od; bi = oi; }
    }
    if (j0 == 0) sbi[t] = bi;
    __syncthreads();

    int w = tid >> 5, lane = tid & 31;
    #pragma unroll
    for (int rr = 0; rr < 2; rr++) {
        int r = w * 2 + rr;
        const float4* er = reinterpret_cast<const float4*>(emb + (size_t)sbi[r] * ND);
        #pragma unroll
        for (int u = 0; u < 2; u++)
            *reinterpret_cast<float4*>(qs + r * QST + u * 128 + lane * 4) = er[u * 32 + lane];
    }
    __syncthreads();

    float* ob = out + (size_t)b * ND * NTHW + p0;
    double lacc = 0.0;
    #pragma unroll
    for (int i = 0; i < 4; i++) {
        int o  = tid + i * 256;          // [0, 1024)
        int c  = o >> 2, t4 = (o & 3) * 4;
        float4 xv = *reinterpret_cast<const float4*>(xs + c * RST + t4);
        float d0 = __fsub_rn(qs[(t4 + 0) * QST + c], xv.x);
        float d1 = __fsub_rn(qs[(t4 + 1) * QST + c], xv.y);
        float d2 = __fsub_rn(qs[(t4 + 2) * QST + c], xv.z);
        float d3 = __fsub_rn(qs[(t4 + 3) * QST + c], xv.w);
        float4 ov;
        ov.x = __fadd_rn(xv.x, d0); ov.y = __fadd_rn(xv.y, d1);
        ov.z = __fadd_rn(xv.z, d2); ov.w = __fadd_rn(xv.w, d3);
        *reinterpret_cast<float4*>(ob + (size_t)c * NTHW + t4) = ov;
        lacc += (double)__fmul_rn(d0, d0) + (double)__fmul_rn(d1, d1)
              + (double)__fmul_rn(d2, d2) + (double)__fmul_rn(d3, d3);
    }
    #pragma unroll
    for (int off = 16; off > 0; off >>= 1)
        lacc += __shfl_down_sync(0xffffffffu, lacc, off);
    if (lane == 0) red[w] = lacc;
    __syncthreads();
    if (tid == 0) {
        double s = 0.0;
        #pragma unroll
        for (int i = 0; i < 8; i++) s += red[i];
        atomicAdd(&g_loss, s);
    }
}

// ---------------------------------------------------------------------------
// Kernel 3: finalize loss
// ---------------------------------------------------------------------------
__global__ void k_final(float* __restrict__ out, int out_size) {
    if (out_size > NTOT) {
        float m = (float)(g_loss / (double)NTOT);
        out[NTOT] = __fadd_rn(m, __fmul_rn(0.25f, m));
    }
}

// ---------------------------------------------------------------------------
extern "C" void kernel_launch(void* const* d_in, const int* in_sizes, int n_in,
                              void* d_out, int out_size) {
    const float* x   = (const float*)d_in[0];
    const float* emb = (const float*)d_in[1];
    if (n_in >= 2 && in_sizes[0] == NK * ND && in_sizes[1] == NTOT) {
        x   = (const float*)d_in[1];
        emb = (const float*)d_in[0];
    }
    float* out = (float*)d_out;

    cudaFuncSetAttribute(k_screen, cudaFuncAttributeMaxDynamicSharedMemorySize, SMEM_SCREEN);
    cudaFuncSetAttribute(k_resg,   cudaFuncAttributeMaxDynamicSharedMemorySize, SMEM_RESG);

    k_init  <<<NK / 8, 256>>>(emb);
    k_screen<<<NTOK / MT, 256, SMEM_SCREEN>>>(x);
    k_resg  <<<NTOK / RT, 256, SMEM_RESG>>>(x, emb, out);
    k_final <<<1, 1>>>(out, out_size);
}